// round 6
// baseline (speedup 1.0000x reference)
#include <cuda_runtime.h>
#include <cuda_bf16.h>
#include <cstdint>

#define N_NODES 20000
#define N_EDGES 320000
#define IN_FEATS 512
#define HIDDEN 64
#define HEADS 8
#define D0 512           // HEADS*HIDDEN
#define OUT_DIM 64
#define NEG_SLOPE 0.2f
#define MAXDEG 512

// ---------------- scratch (device globals; no allocation allowed) ----------------
__device__ float g_feat0[(size_t)N_NODES * D0];      // layer0 projected feats [N, 8*64]
__device__ float g_feat1[(size_t)N_NODES * OUT_DIM]; // layer1 projected feats [N, 64]
__device__ float g_spA_h[(size_t)N_NODES * D0];      // tf32-split A (features, then elu(h1))
__device__ float g_spA_l[(size_t)N_NODES * D0];
__device__ float g_spB_h[IN_FEATS * D0];             // tf32-split W (W0, then W1)
__device__ float g_spB_l[IN_FEATS * D0];
__device__ float g_el0[N_NODES * HEADS];
__device__ float g_er0[N_NODES * HEADS];
__device__ float g_el1[N_NODES];
__device__ float g_er1[N_NODES];
__device__ int   g_counts[N_NODES];
__device__ int   g_rowoff[N_NODES + 1];
__device__ int   g_cursor[N_NODES];
__device__ int   g_csrsrc[N_EDGES];

__device__ __forceinline__ float lrelu(float x) { return x > 0.f ? x : NEG_SLOPE * x; }
#define NEG_INF __int_as_float(0xff800000)

__device__ __forceinline__ void tf32split(float v, uint32_t& h, uint32_t& l) {
    uint32_t uh;
    asm("cvt.rna.tf32.f32 %0, %1;" : "=r"(uh) : "f"(v));
    float fl = v - __uint_as_float(uh);
    uint32_t ul;
    asm("cvt.rna.tf32.f32 %0, %1;" : "=r"(ul) : "f"(fl));
    h = uh; l = ul;
}

// ---------------- CSR build ----------------
__global__ void zero_counts_kernel() {
    int i = blockIdx.x * blockDim.x + threadIdx.x;
    if (i < N_NODES) g_counts[i] = 0;
}

__global__ void count_kernel(const int* __restrict__ dst) {
    int e = blockIdx.x * blockDim.x + threadIdx.x;
    if (e < N_EDGES) atomicAdd(&g_counts[dst[e]], 1);
}

__global__ void scan_kernel() {
    __shared__ int s[1024];
    const int tid = threadIdx.x;
    const int CH = (N_NODES + 1023) / 1024;   // 20
    int b = tid * CH;
    int e = min(b + CH, N_NODES);
    int local = 0;
    for (int i = b; i < e; i++) local += g_counts[i];
    s[tid] = local;
    __syncthreads();
    for (int off = 1; off < 1024; off <<= 1) {
        int add = (tid >= off) ? s[tid - off] : 0;
        __syncthreads();
        s[tid] += add;
        __syncthreads();
    }
    int run = s[tid] - local;                 // exclusive prefix
    for (int i = b; i < e; i++) {
        g_rowoff[i] = run;
        g_cursor[i] = run;
        run += g_counts[i];
    }
    if (tid == 1023) g_rowoff[N_NODES] = s[1023];
}

__global__ void scatter_kernel(const int* __restrict__ src, const int* __restrict__ dst) {
    int e = blockIdx.x * blockDim.x + threadIdx.x;
    if (e < N_EDGES) {
        int pos = atomicAdd(&g_cursor[dst[e]], 1);
        g_csrsrc[pos] = src[e];
    }
}

// ---------------- tf32 pre-split: v -> (hi, lo) as fp32-compatible bit patterns ----------------
__global__ void split_tf32_kernel(const float4* __restrict__ in,
                                  float4* __restrict__ hi, float4* __restrict__ lo, int n4)
{
    int i = blockIdx.x * blockDim.x + threadIdx.x;
    if (i >= n4) return;
    float4 v = in[i];
    uint32_t hx, lx, hy, ly, hz, lz, hw, lw;
    tf32split(v.x, hx, lx);
    tf32split(v.y, hy, ly);
    tf32split(v.z, hz, lz);
    tf32split(v.w, hw, lw);
    hi[i] = make_float4(__uint_as_float(hx), __uint_as_float(hy),
                        __uint_as_float(hz), __uint_as_float(hw));
    lo[i] = make_float4(__uint_as_float(lx), __uint_as_float(ly),
                        __uint_as_float(lz), __uint_as_float(lw));
}

// ================= pure-tf32 3-term tensor-core GEMM (pre-split inputs) =================
// C[M,N] = A[M,K]*B[K,N] with A=Ah+Al, B=Bh+Bl already split to tf32.
// C ~= Ah*Bh + Ah*Bl + Al*Bh. Tiles: BM=128, BN=64, BK=16; 256 thr = 8 warps, 32x32/warp.
#define TBM 128
#define TBN 64
#define TBK 16
#define A_STRIDE 20
#define B_STRIDE 72
#define SA_BUF (TBM * A_STRIDE)           // floats per buffer
#define SB_BUF (TBK * B_STRIDE)
#define GEMM_SMEM ((2 * SA_BUF * 2 + 2 * SB_BUF * 2) * 4)   // bytes = 59392

__device__ __forceinline__ void cpasync16(void* smem, const void* g, bool valid) {
    uint32_t sa = (uint32_t)__cvta_generic_to_shared(smem);
    int sz = valid ? 16 : 0;
    asm volatile("cp.async.cg.shared.global [%0], [%1], 16, %2;" :: "r"(sa), "l"(g), "r"(sz));
}

__device__ __forceinline__ void mma8(float* c, const uint32_t* a, const uint32_t* b) {
    asm volatile(
        "mma.sync.aligned.m16n8k8.row.col.f32.tf32.tf32.f32 "
        "{%0,%1,%2,%3}, {%4,%5,%6,%7}, {%8,%9}, {%0,%1,%2,%3};"
        : "+f"(c[0]), "+f"(c[1]), "+f"(c[2]), "+f"(c[3])
        : "r"(a[0]), "r"(a[1]), "r"(a[2]), "r"(a[3]), "r"(b[0]), "r"(b[1]));
}

__global__ void __launch_bounds__(256, 2) tf32ps_gemm_kernel(
    const float* __restrict__ Ah, const float* __restrict__ Al,
    const float* __restrict__ Bh, const float* __restrict__ Bl,
    float* __restrict__ C, int M, int N, int K)
{
    extern __shared__ float sm[];
    float* sAh = sm;
    float* sAl = sAh + 2 * SA_BUF;
    float* sBh = sAl + 2 * SA_BUF;
    float* sBl = sBh + 2 * SB_BUF;

    const int bm = blockIdx.y * TBM;
    const int bn = blockIdx.x * TBN;
    const int tid = threadIdx.x;
    const int lane = tid & 31;
    const int warp = tid >> 5;
    const int wm = warp >> 1;       // 0..3
    const int wn = warp & 1;        // 0..1
    const int quad = lane >> 2;     // 0..7
    const int kq = lane & 3;        // 0..3

    const int a_m  = tid >> 2;            // 0..63  (two passes: +64)
    const int a_kc = (tid & 3) << 2;      // 0,4,8,12
    const int b_k  = tid >> 4;            // 0..15
    const int b_nc = (tid & 15) << 2;     // 0..60

    float acc[2][4][4];
#pragma unroll
    for (int mi = 0; mi < 2; mi++)
#pragma unroll
        for (int ni = 0; ni < 4; ni++)
#pragma unroll
            for (int r = 0; r < 4; r++) acc[mi][ni][r] = 0.f;

    const int T = K / TBK;

    // ---- prologue: stage tile 0 into buffer 0 ----
    {
#pragma unroll
        for (int p = 0; p < 2; p++) {
            int m = a_m + (p << 6);
            bool ok = (bm + m) < M;
            size_t go = (size_t)(bm + m) * K + a_kc;
            int so = m * A_STRIDE + a_kc;
            cpasync16(&sAh[so], Ah + go, ok);
            cpasync16(&sAl[so], Al + go, ok);
        }
        size_t gbo = (size_t)b_k * N + bn + b_nc;
        int sbo = b_k * B_STRIDE + b_nc;
        cpasync16(&sBh[sbo], Bh + gbo, true);
        cpasync16(&sBl[sbo], Bl + gbo, true);
        asm volatile("cp.async.commit_group;");
    }

    for (int t = 0; t < T; t++) {
        const int cur = t & 1;
        if (t + 1 < T) {
            const int nxt = cur ^ 1;
            const int kt = (t + 1) * TBK;
#pragma unroll
            for (int p = 0; p < 2; p++) {
                int m = a_m + (p << 6);
                bool ok = (bm + m) < M;
                size_t go = (size_t)(bm + m) * K + kt + a_kc;
                int so = nxt * SA_BUF + m * A_STRIDE + a_kc;
                cpasync16(&sAh[so], Ah + go, ok);
                cpasync16(&sAl[so], Al + go, ok);
            }
            size_t gbo = (size_t)(kt + b_k) * N + bn + b_nc;
            int sbo = nxt * SB_BUF + b_k * B_STRIDE + b_nc;
            cpasync16(&sBh[sbo], Bh + gbo, true);
            cpasync16(&sBl[sbo], Bl + gbo, true);
            asm volatile("cp.async.commit_group;");
            asm volatile("cp.async.wait_group 1;");
        } else {
            asm volatile("cp.async.wait_group 0;");
        }
        __syncthreads();

#pragma unroll
        for (int ks = 0; ks < 2; ks++) {
            const int kb = ks * 8 + kq;
            uint32_t ah[2][4], al_[2][4];
#pragma unroll
            for (int mi = 0; mi < 2; mi++) {
#pragma unroll
                for (int r = 0; r < 4; r++) {
                    int row = wm * 32 + mi * 16 + quad + ((r & 1) << 3);
                    int col = kb + ((r >> 1) << 2);
                    int idx = cur * SA_BUF + row * A_STRIDE + col;
                    ah[mi][r]  = __float_as_uint(sAh[idx]);
                    al_[mi][r] = __float_as_uint(sAl[idx]);
                }
            }
            uint32_t bh[4][2], bl[4][2];
#pragma unroll
            for (int ni = 0; ni < 4; ni++) {
#pragma unroll
                for (int r = 0; r < 2; r++) {
                    int krow = kb + (r << 2);
                    int ncol = wn * 32 + ni * 8 + quad;
                    int idx = cur * SB_BUF + krow * B_STRIDE + ncol;
                    bh[ni][r] = __float_as_uint(sBh[idx]);
                    bl[ni][r] = __float_as_uint(sBl[idx]);
                }
            }
            // three terms, 8 independent accs between reuses of each acc
#pragma unroll
            for (int mi = 0; mi < 2; mi++)
#pragma unroll
                for (int ni = 0; ni < 4; ni++) mma8(acc[mi][ni], ah[mi], bh[ni]);
#pragma unroll
            for (int mi = 0; mi < 2; mi++)
#pragma unroll
                for (int ni = 0; ni < 4; ni++) mma8(acc[mi][ni], ah[mi], bl[ni]);
#pragma unroll
            for (int mi = 0; mi < 2; mi++)
#pragma unroll
                for (int ni = 0; ni < 4; ni++) mma8(acc[mi][ni], al_[mi], bh[ni]);
        }
        __syncthreads();
    }

    // ---- epilogue ----
#pragma unroll
    for (int mi = 0; mi < 2; mi++) {
#pragma unroll
        for (int ni = 0; ni < 4; ni++) {
            int row0 = bm + wm * 32 + mi * 16 + quad;
            int col = bn + wn * 32 + ni * 8 + kq * 2;
            if (row0 < M)
                *(float2*)(C + (size_t)row0 * N + col) =
                    make_float2(acc[mi][ni][0], acc[mi][ni][1]);
            int row1 = row0 + 8;
            if (row1 < M)
                *(float2*)(C + (size_t)row1 * N + col) =
                    make_float2(acc[mi][ni][2], acc[mi][ni][3]);
        }
    }
}

// ---------------- el/er for layer 0: warp per (node, head) ----------------
__global__ void __launch_bounds__(256) eler0_kernel(const float* __restrict__ al,
                                                    const float* __restrict__ ar)
{
    const int n = blockIdx.x;
    const int h = threadIdx.x >> 5;
    const int lane = threadIdx.x & 31;
    const float* f = g_feat0 + (size_t)n * D0 + h * HIDDEN;
    float2 fv = *(const float2*)(f + lane * 2);
    float2 alv = *(const float2*)(al + h * HIDDEN + lane * 2);
    float2 arv = *(const float2*)(ar + h * HIDDEN + lane * 2);
    float sl = fv.x * alv.x + fv.y * alv.y;
    float sr = fv.x * arv.x + fv.y * arv.y;
#pragma unroll
    for (int o = 16; o; o >>= 1) {
        sl += __shfl_xor_sync(0xffffffffu, sl, o);
        sr += __shfl_xor_sync(0xffffffffu, sr, o);
    }
    if (lane == 0) {
        g_el0[n * HEADS + h] = sl;
        g_er0[n * HEADS + h] = sr;
    }
}

// ---------------- el/er for layer 1: warp per node ----------------
__global__ void __launch_bounds__(256) eler1_kernel(const float* __restrict__ al,
                                                    const float* __restrict__ ar)
{
    const int gw = blockIdx.x * 8 + (threadIdx.x >> 5);
    const int lane = threadIdx.x & 31;
    if (gw >= N_NODES) return;
    const float* f = g_feat1 + (size_t)gw * OUT_DIM;
    float2 fv = *(const float2*)(f + lane * 2);
    float2 alv = *(const float2*)(al + lane * 2);
    float2 arv = *(const float2*)(ar + lane * 2);
    float sl = fv.x * alv.x + fv.y * alv.y;
    float sr = fv.x * arv.x + fv.y * arv.y;
#pragma unroll
    for (int o = 16; o; o >>= 1) {
        sl += __shfl_xor_sync(0xffffffffu, sl, o);
        sr += __shfl_xor_sync(0xffffffffu, sr, o);
    }
    if (lane == 0) {
        g_el1[gw] = sl;
        g_er1[gw] = sr;
    }
}

// ---- fused store: elu(x) written as tf32 hi/lo split (h1 only feeds GEMM1) ----
__device__ __forceinline__ void store_elu_split(size_t idx, float v) {
    float e = v > 0.f ? v : __expf(v) - 1.f;
    uint32_t h, l;
    tf32split(e, h, l);
    g_spA_h[idx] = __uint_as_float(h);
    g_spA_l[idx] = __uint_as_float(l);
}

// ---------------- layer-0 softmax + aggregation + ELU + split: block per dst ----------------
__global__ void __launch_bounds__(256) gat_agg0_kernel()
{
    const int n = blockIdx.x;
    const int beg = g_rowoff[n];
    const int deg = g_rowoff[n + 1] - beg;
    const int tid = threadIdx.x;

    if (deg == 0) {   // elu(0) = 0 -> split(0) = (0,0)
        g_spA_h[(size_t)n * D0 + tid] = 0.f;
        g_spA_l[(size_t)n * D0 + tid] = 0.f;
        g_spA_h[(size_t)n * D0 + tid + 256] = 0.f;
        g_spA_l[(size_t)n * D0 + tid + 256] = 0.f;
        return;
    }

    __shared__ float s_alpha[HEADS][MAXDEG];
    __shared__ int   s_src[MAXDEG];
    __shared__ float s_m[HEADS], s_rinv[HEADS];

    const int h = tid >> 5;
    const int lane = tid & 31;
    const float ern = g_er0[n * HEADS + h];

    const int c0 = tid, c1 = tid + 256;
    const int h0 = c0 >> 6, h1i = c1 >> 6;

    if (deg <= MAXDEG) {
        for (int j = tid; j < deg; j += 256) s_src[j] = g_csrsrc[beg + j];
        __syncthreads();

        float m = NEG_INF;
        for (int j = lane; j < deg; j += 32) {
            float e = lrelu(g_el0[s_src[j] * HEADS + h] + ern);
            s_alpha[h][j] = e;
            m = fmaxf(m, e);
        }
#pragma unroll
        for (int o = 16; o; o >>= 1) m = fmaxf(m, __shfl_xor_sync(0xffffffffu, m, o));
        float sum = 0.f;
        for (int j = lane; j < deg; j += 32) {
            float ex = __expf(s_alpha[h][j] - m);
            s_alpha[h][j] = ex;
            sum += ex;
        }
#pragma unroll
        for (int o = 16; o; o >>= 1) sum += __shfl_xor_sync(0xffffffffu, sum, o);
        float rinv = 1.f / fmaxf(sum, 1e-9f);
        for (int j = lane; j < deg; j += 32) s_alpha[h][j] *= rinv;
        __syncthreads();

        float acc0 = 0.f, acc1 = 0.f;
#pragma unroll 4
        for (int j = 0; j < deg; j++) {
            const float* fr = g_feat0 + (size_t)s_src[j] * D0;
            acc0 = fmaf(s_alpha[h0][j], fr[c0], acc0);
            acc1 = fmaf(s_alpha[h1i][j], fr[c1], acc1);
        }
        store_elu_split((size_t)n * D0 + c0, acc0);
        store_elu_split((size_t)n * D0 + c1, acc1);
    } else {
        // huge-degree fallback: recompute e, no SMEM caches
        float m = NEG_INF;
        for (int j = lane; j < deg; j += 32)
            m = fmaxf(m, lrelu(g_el0[g_csrsrc[beg + j] * HEADS + h] + ern));
#pragma unroll
        for (int o = 16; o; o >>= 1) m = fmaxf(m, __shfl_xor_sync(0xffffffffu, m, o));
        float sum = 0.f;
        for (int j = lane; j < deg; j += 32)
            sum += __expf(lrelu(g_el0[g_csrsrc[beg + j] * HEADS + h] + ern) - m);
#pragma unroll
        for (int o = 16; o; o >>= 1) sum += __shfl_xor_sync(0xffffffffu, sum, o);
        if (lane == 0) { s_m[h] = m; s_rinv[h] = 1.f / fmaxf(sum, 1e-9f); }
        __syncthreads();

        const float m0 = s_m[h0], r0 = s_rinv[h0];
        const float m1 = s_m[h1i], r1 = s_rinv[h1i];
        const float e0n = g_er0[n * HEADS + h0], e1n = g_er0[n * HEADS + h1i];
        float acc0 = 0.f, acc1 = 0.f;
        for (int j = 0; j < deg; j++) {
            int s = g_csrsrc[beg + j];
            float a0 = __expf(lrelu(g_el0[s * HEADS + h0] + e0n) - m0) * r0;
            float a1 = __expf(lrelu(g_el0[s * HEADS + h1i] + e1n) - m1) * r1;
            const float* fr = g_feat0 + (size_t)s * D0;
            acc0 = fmaf(a0, fr[c0], acc0);
            acc1 = fmaf(a1, fr[c1], acc1);
        }
        store_elu_split((size_t)n * D0 + c0, acc0);
        store_elu_split((size_t)n * D0 + c1, acc1);
    }
}

// ---------------- layer-1 softmax + aggregation (1 head, 64 dims): block per dst ----------------
__global__ void __launch_bounds__(64) gat_agg1_kernel(float* __restrict__ out)
{
    const int n = blockIdx.x;
    const int beg = g_rowoff[n];
    const int deg = g_rowoff[n + 1] - beg;
    const int tid = threadIdx.x;

    if (deg == 0) { out[(size_t)n * OUT_DIM + tid] = 0.f; return; }

    __shared__ float s_alpha[MAXDEG];
    __shared__ int   s_src[MAXDEG];
    __shared__ float s_mr[2];

    const float ern = g_er1[n];

    if (deg <= MAXDEG) {
        for (int j = tid; j < deg; j += 64) s_src[j] = g_csrsrc[beg + j];
        __syncthreads();
        if (tid < 32) {
            float m = NEG_INF;
            for (int j = tid; j < deg; j += 32) {
                float e = lrelu(g_el1[s_src[j]] + ern);
                s_alpha[j] = e;
                m = fmaxf(m, e);
            }
#pragma unroll
            for (int o = 16; o; o >>= 1) m = fmaxf(m, __shfl_xor_sync(0xffffffffu, m, o));
            float sum = 0.f;
            for (int j = tid; j < deg; j += 32) {
                float ex = __expf(s_alpha[j] - m);
                s_alpha[j] = ex;
                sum += ex;
            }
#pragma unroll
            for (int o = 16; o; o >>= 1) sum += __shfl_xor_sync(0xffffffffu, sum, o);
            float rinv = 1.f / fmaxf(sum, 1e-9f);
            for (int j = tid; j < deg; j += 32) s_alpha[j] *= rinv;
        }
        __syncthreads();
        float acc = 0.f;
#pragma unroll 4
        for (int j = 0; j < deg; j++)
            acc = fmaf(s_alpha[j], g_feat1[(size_t)s_src[j] * OUT_DIM + tid], acc);
        out[(size_t)n * OUT_DIM + tid] = acc;
    } else {
        if (tid < 32) {
            float m = NEG_INF;
            for (int j = tid; j < deg; j += 32)
                m = fmaxf(m, lrelu(g_el1[g_csrsrc[beg + j]] + ern));
#pragma unroll
            for (int o = 16; o; o >>= 1) m = fmaxf(m, __shfl_xor_sync(0xffffffffu, m, o));
            float sum = 0.f;
            for (int j = tid; j < deg; j += 32)
                sum += __expf(lrelu(g_el1[g_csrsrc[beg + j]] + ern) - m);
#pragma unroll
            for (int o = 16; o; o >>= 1) sum += __shfl_xor_sync(0xffffffffu, sum, o);
            if (tid == 0) { s_mr[0] = m; s_mr[1] = 1.f / fmaxf(sum, 1e-9f); }
        }
        __syncthreads();
        const float m = s_mr[0], rinv = s_mr[1];
        float acc = 0.f;
        for (int j = 0; j < deg; j++) {
            int s = g_csrsrc[beg + j];
            float a = __expf(lrelu(g_el1[s] + ern) - m) * rinv;
            acc = fmaf(a, g_feat1[(size_t)s * OUT_DIM + tid], acc);
        }
        out[(size_t)n * OUT_DIM + tid] = acc;
    }
}

// ---------------- launch ----------------
extern "C" void kernel_launch(void* const* d_in, const int* in_sizes, int n_in,
                              void* d_out, int out_size)
{
    const float* features = (const float*)d_in[0];
    const int*   src      = (const int*)d_in[1];
    const int*   dst      = (const int*)d_in[2];
    const float* W0       = (const float*)d_in[3];
    const float* al0      = (const float*)d_in[4];
    const float* ar0      = (const float*)d_in[5];
    const float* W1       = (const float*)d_in[6];
    const float* al1      = (const float*)d_in[7];
    const float* ar1      = (const float*)d_in[8];
    float* out = (float*)d_out;

    float *feat0p = nullptr, *feat1p = nullptr;
    float *spAh = nullptr, *spAl = nullptr, *spBh = nullptr, *spBl = nullptr;
    cudaGetSymbolAddress((void**)&feat0p, g_feat0);
    cudaGetSymbolAddress((void**)&feat1p, g_feat1);
    cudaGetSymbolAddress((void**)&spAh,   g_spA_h);
    cudaGetSymbolAddress((void**)&spAl,   g_spA_l);
    cudaGetSymbolAddress((void**)&spBh,   g_spB_h);
    cudaGetSymbolAddress((void**)&spBl,   g_spB_l);

    cudaFuncSetAttribute(tf32ps_gemm_kernel,
                         cudaFuncAttributeMaxDynamicSharedMemorySize, GEMM_SMEM);

    // CSR by dst
    zero_counts_kernel<<<(N_NODES + 255) / 256, 256>>>();
    count_kernel<<<(N_EDGES + 255) / 256, 256>>>(dst);
    scan_kernel<<<1, 1024>>>();
    scatter_kernel<<<(N_EDGES + 255) / 256, 256>>>(src, dst);

    const int mblocks = (N_NODES + TBM - 1) / TBM;   // 157

    // layer 0: pre-split inputs, then pure-tf32 GEMM
    {
        int n4 = N_NODES * IN_FEATS / 4;
        split_tf32_kernel<<<(n4 + 255) / 256, 256>>>(
            (const float4*)features, (float4*)spAh, (float4*)spAl, n4);
        int w4 = IN_FEATS * D0 / 4;
        split_tf32_kernel<<<(w4 + 255) / 256, 256>>>(
            (const float4*)W0, (float4*)spBh, (float4*)spBl, w4);
    }
    tf32ps_gemm_kernel<<<dim3(D0 / TBN, mblocks), 256, GEMM_SMEM>>>(
        spAh, spAl, spBh, spBl, feat0p, N_NODES, D0, IN_FEATS);
    eler0_kernel<<<N_NODES, 256>>>(al0, ar0);
    gat_agg0_kernel<<<N_NODES, 256>>>();   // writes elu(h1) splits into spA

    // layer 1: split W1 (spA already holds split elu(h1))
    {
        int w4 = D0 * OUT_DIM / 4;
        split_tf32_kernel<<<(w4 + 255) / 256, 256>>>(
            (const float4*)W1, (float4*)spBh, (float4*)spBl, w4);
    }
    tf32ps_gemm_kernel<<<dim3(OUT_DIM / TBN, mblocks), 256, GEMM_SMEM>>>(
        spAh, spAl, spBh, spBl, feat1p, N_NODES, OUT_DIM, D0);
    eler1_kernel<<<(N_NODES + 7) / 8, 256>>>(al1, ar1);
    gat_agg1_kernel<<<N_NODES, 64>>>(out);
}

// round 7
// speedup vs baseline: 1.0004x; 1.0004x over previous
#include <cuda_runtime.h>
#include <cuda_bf16.h>
#include <cstdint>

#define N_NODES 20000
#define N_EDGES 320000
#define IN_FEATS 512
#define HIDDEN 64
#define HEADS 8
#define D0 512           // HEADS*HIDDEN
#define OUT_DIM 64
#define NEG_SLOPE 0.2f
#define MAXDEG 512

// ---------------- scratch (device globals; no allocation allowed) ----------------
__device__ float g_feat0[(size_t)N_NODES * D0];      // layer0 projected feats [N, 8*64]
__device__ float g_feat1[(size_t)N_NODES * OUT_DIM]; // layer1 projected feats [N, 64]
__device__ float g_spA_h[(size_t)N_NODES * D0];      // tf32-split A (features, then elu(h1))
__device__ float g_spA_l[(size_t)N_NODES * D0];
__device__ float g_spB_h[IN_FEATS * D0];             // tf32-split W (W0, then W1)
__device__ float g_spB_l[IN_FEATS * D0];
__device__ float g_el0[N_NODES * HEADS];
__device__ float g_er0[N_NODES * HEADS];
__device__ float g_el1[N_NODES];
__device__ float g_er1[N_NODES];
__device__ int   g_counts[N_NODES];
__device__ int   g_rowoff[N_NODES + 1];
__device__ int   g_cursor[N_NODES];
__device__ int   g_csrsrc[N_EDGES];

__device__ __forceinline__ float lrelu(float x) { return x > 0.f ? x : NEG_SLOPE * x; }
#define NEG_INF __int_as_float(0xff800000)

__device__ __forceinline__ void tf32split(float v, uint32_t& h, uint32_t& l) {
    uint32_t uh;
    asm("cvt.rna.tf32.f32 %0, %1;" : "=r"(uh) : "f"(v));
    float fl = v - __uint_as_float(uh);
    uint32_t ul;
    asm("cvt.rna.tf32.f32 %0, %1;" : "=r"(ul) : "f"(fl));
    h = uh; l = ul;
}

// ---------------- CSR build ----------------
__global__ void zero_counts_kernel() {
    int i = blockIdx.x * blockDim.x + threadIdx.x;
    if (i < N_NODES) g_counts[i] = 0;
}

__global__ void count_kernel(const int* __restrict__ dst) {
    int e = blockIdx.x * blockDim.x + threadIdx.x;
    if (e < N_EDGES) atomicAdd(&g_counts[dst[e]], 1);
}

__global__ void scan_kernel() {
    __shared__ int s[1024];
    const int tid = threadIdx.x;
    const int CH = (N_NODES + 1023) / 1024;   // 20
    int b = tid * CH;
    int e = min(b + CH, N_NODES);
    int local = 0;
    for (int i = b; i < e; i++) local += g_counts[i];
    s[tid] = local;
    __syncthreads();
    for (int off = 1; off < 1024; off <<= 1) {
        int add = (tid >= off) ? s[tid - off] : 0;
        __syncthreads();
        s[tid] += add;
        __syncthreads();
    }
    int run = s[tid] - local;                 // exclusive prefix
    for (int i = b; i < e; i++) {
        g_rowoff[i] = run;
        g_cursor[i] = run;
        run += g_counts[i];
    }
    if (tid == 1023) g_rowoff[N_NODES] = s[1023];
}

__global__ void scatter_kernel(const int* __restrict__ src, const int* __restrict__ dst) {
    int e = blockIdx.x * blockDim.x + threadIdx.x;
    if (e < N_EDGES) {
        int pos = atomicAdd(&g_cursor[dst[e]], 1);
        g_csrsrc[pos] = src[e];
    }
}

// ---------------- tf32 pre-split: v -> (hi, lo) as fp32-compatible bit patterns ----------------
__global__ void split_tf32_kernel(const float4* __restrict__ in,
                                  float4* __restrict__ hi, float4* __restrict__ lo, int n4)
{
    int i = blockIdx.x * blockDim.x + threadIdx.x;
    if (i >= n4) return;
    float4 v = in[i];
    uint32_t hx, lx, hy, ly, hz, lz, hw, lw;
    tf32split(v.x, hx, lx);
    tf32split(v.y, hy, ly);
    tf32split(v.z, hz, lz);
    tf32split(v.w, hw, lw);
    hi[i] = make_float4(__uint_as_float(hx), __uint_as_float(hy),
                        __uint_as_float(hz), __uint_as_float(hw));
    lo[i] = make_float4(__uint_as_float(lx), __uint_as_float(ly),
                        __uint_as_float(lz), __uint_as_float(lw));
}

// ================= pure-tf32 3-term tensor-core GEMM (pre-split inputs) =================
// C[M,N] = A[M,K]*B[K,N] with A=Ah+Al, B=Bh+Bl already split to tf32.
// C ~= Ah*Bh + Ah*Bl + Al*Bh. Tiles: BM=128, BN=64, BK=16; 256 thr = 8 warps, 32x32/warp.
#define TBM 128
#define TBN 64
#define TBK 16
#define A_STRIDE 20
#define B_STRIDE 72
#define SA_BUF (TBM * A_STRIDE)           // floats per buffer
#define SB_BUF (TBK * B_STRIDE)
#define GEMM_SMEM ((2 * SA_BUF * 2 + 2 * SB_BUF * 2) * 4)   // bytes = 59392

__device__ __forceinline__ void cpasync16(void* smem, const void* g, bool valid) {
    uint32_t sa = (uint32_t)__cvta_generic_to_shared(smem);
    int sz = valid ? 16 : 0;
    asm volatile("cp.async.cg.shared.global [%0], [%1], 16, %2;" :: "r"(sa), "l"(g), "r"(sz));
}

__device__ __forceinline__ void mma8(float* c, const uint32_t* a, const uint32_t* b) {
    asm volatile(
        "mma.sync.aligned.m16n8k8.row.col.f32.tf32.tf32.f32 "
        "{%0,%1,%2,%3}, {%4,%5,%6,%7}, {%8,%9}, {%0,%1,%2,%3};"
        : "+f"(c[0]), "+f"(c[1]), "+f"(c[2]), "+f"(c[3])
        : "r"(a[0]), "r"(a[1]), "r"(a[2]), "r"(a[3]), "r"(b[0]), "r"(b[1]));
}

__global__ void __launch_bounds__(256, 2) tf32ps_gemm_kernel(
    const float* __restrict__ Ah, const float* __restrict__ Al,
    const float* __restrict__ Bh, const float* __restrict__ Bl,
    float* __restrict__ C, int M, int N, int K)
{
    extern __shared__ float sm[];
    float* sAh = sm;
    float* sAl = sAh + 2 * SA_BUF;
    float* sBh = sAl + 2 * SA_BUF;
    float* sBl = sBh + 2 * SB_BUF;

    const int bm = blockIdx.y * TBM;
    const int bn = blockIdx.x * TBN;
    const int tid = threadIdx.x;
    const int lane = tid & 31;
    const int warp = tid >> 5;
    const int wm = warp >> 1;       // 0..3
    const int wn = warp & 1;        // 0..1
    const int quad = lane >> 2;     // 0..7
    const int kq = lane & 3;        // 0..3

    const int a_m  = tid >> 2;            // 0..63  (two passes: +64)
    const int a_kc = (tid & 3) << 2;      // 0,4,8,12
    const int b_k  = tid >> 4;            // 0..15
    const int b_nc = (tid & 15) << 2;     // 0..60

    float acc[2][4][4];
#pragma unroll
    for (int mi = 0; mi < 2; mi++)
#pragma unroll
        for (int ni = 0; ni < 4; ni++)
#pragma unroll
            for (int r = 0; r < 4; r++) acc[mi][ni][r] = 0.f;

    const int T = K / TBK;

    // ---- prologue: stage tile 0 into buffer 0 ----
    {
#pragma unroll
        for (int p = 0; p < 2; p++) {
            int m = a_m + (p << 6);
            bool ok = (bm + m) < M;
            size_t go = (size_t)(bm + m) * K + a_kc;
            int so = m * A_STRIDE + a_kc;
            cpasync16(&sAh[so], Ah + go, ok);
            cpasync16(&sAl[so], Al + go, ok);
        }
        size_t gbo = (size_t)b_k * N + bn + b_nc;
        int sbo = b_k * B_STRIDE + b_nc;
        cpasync16(&sBh[sbo], Bh + gbo, true);
        cpasync16(&sBl[sbo], Bl + gbo, true);
        asm volatile("cp.async.commit_group;");
    }

    for (int t = 0; t < T; t++) {
        const int cur = t & 1;
        if (t + 1 < T) {
            const int nxt = cur ^ 1;
            const int kt = (t + 1) * TBK;
#pragma unroll
            for (int p = 0; p < 2; p++) {
                int m = a_m + (p << 6);
                bool ok = (bm + m) < M;
                size_t go = (size_t)(bm + m) * K + kt + a_kc;
                int so = nxt * SA_BUF + m * A_STRIDE + a_kc;
                cpasync16(&sAh[so], Ah + go, ok);
                cpasync16(&sAl[so], Al + go, ok);
            }
            size_t gbo = (size_t)(kt + b_k) * N + bn + b_nc;
            int sbo = nxt * SB_BUF + b_k * B_STRIDE + b_nc;
            cpasync16(&sBh[sbo], Bh + gbo, true);
            cpasync16(&sBl[sbo], Bl + gbo, true);
            asm volatile("cp.async.commit_group;");
            asm volatile("cp.async.wait_group 1;");
        } else {
            asm volatile("cp.async.wait_group 0;");
        }
        __syncthreads();

#pragma unroll
        for (int ks = 0; ks < 2; ks++) {
            const int kb = ks * 8 + kq;
            uint32_t ah[2][4], al_[2][4];
#pragma unroll
            for (int mi = 0; mi < 2; mi++) {
#pragma unroll
                for (int r = 0; r < 4; r++) {
                    int row = wm * 32 + mi * 16 + quad + ((r & 1) << 3);
                    int col = kb + ((r >> 1) << 2);
                    int idx = cur * SA_BUF + row * A_STRIDE + col;
                    ah[mi][r]  = __float_as_uint(sAh[idx]);
                    al_[mi][r] = __float_as_uint(sAl[idx]);
                }
            }
            uint32_t bh[4][2], bl[4][2];
#pragma unroll
            for (int ni = 0; ni < 4; ni++) {
#pragma unroll
                for (int r = 0; r < 2; r++) {
                    int krow = kb + (r << 2);
                    int ncol = wn * 32 + ni * 8 + quad;
                    int idx = cur * SB_BUF + krow * B_STRIDE + ncol;
                    bh[ni][r] = __float_as_uint(sBh[idx]);
                    bl[ni][r] = __float_as_uint(sBl[idx]);
                }
            }
            // three terms, 8 independent accs between reuses of each acc
#pragma unroll
            for (int mi = 0; mi < 2; mi++)
#pragma unroll
                for (int ni = 0; ni < 4; ni++) mma8(acc[mi][ni], ah[mi], bh[ni]);
#pragma unroll
            for (int mi = 0; mi < 2; mi++)
#pragma unroll
                for (int ni = 0; ni < 4; ni++) mma8(acc[mi][ni], ah[mi], bl[ni]);
#pragma unroll
            for (int mi = 0; mi < 2; mi++)
#pragma unroll
                for (int ni = 0; ni < 4; ni++) mma8(acc[mi][ni], al_[mi], bh[ni]);
        }
        __syncthreads();
    }

    // ---- epilogue ----
#pragma unroll
    for (int mi = 0; mi < 2; mi++) {
#pragma unroll
        for (int ni = 0; ni < 4; ni++) {
            int row0 = bm + wm * 32 + mi * 16 + quad;
            int col = bn + wn * 32 + ni * 8 + kq * 2;
            if (row0 < M)
                *(float2*)(C + (size_t)row0 * N + col) =
                    make_float2(acc[mi][ni][0], acc[mi][ni][1]);
            int row1 = row0 + 8;
            if (row1 < M)
                *(float2*)(C + (size_t)row1 * N + col) =
                    make_float2(acc[mi][ni][2], acc[mi][ni][3]);
        }
    }
}

// ---------------- el/er for layer 0: warp per (node, head) ----------------
__global__ void __launch_bounds__(256) eler0_kernel(const float* __restrict__ al,
                                                    const float* __restrict__ ar)
{
    const int n = blockIdx.x;
    const int h = threadIdx.x >> 5;
    const int lane = threadIdx.x & 31;
    const float* f = g_feat0 + (size_t)n * D0 + h * HIDDEN;
    float2 fv = *(const float2*)(f + lane * 2);
    float2 alv = *(const float2*)(al + h * HIDDEN + lane * 2);
    float2 arv = *(const float2*)(ar + h * HIDDEN + lane * 2);
    float sl = fv.x * alv.x + fv.y * alv.y;
    float sr = fv.x * arv.x + fv.y * arv.y;
#pragma unroll
    for (int o = 16; o; o >>= 1) {
        sl += __shfl_xor_sync(0xffffffffu, sl, o);
        sr += __shfl_xor_sync(0xffffffffu, sr, o);
    }
    if (lane == 0) {
        g_el0[n * HEADS + h] = sl;
        g_er0[n * HEADS + h] = sr;
    }
}

// ---------------- el/er for layer 1: warp per node ----------------
__global__ void __launch_bounds__(256) eler1_kernel(const float* __restrict__ al,
                                                    const float* __restrict__ ar)
{
    const int gw = blockIdx.x * 8 + (threadIdx.x >> 5);
    const int lane = threadIdx.x & 31;
    if (gw >= N_NODES) return;
    const float* f = g_feat1 + (size_t)gw * OUT_DIM;
    float2 fv = *(const float2*)(f + lane * 2);
    float2 alv = *(const float2*)(al + lane * 2);
    float2 arv = *(const float2*)(ar + lane * 2);
    float sl = fv.x * alv.x + fv.y * alv.y;
    float sr = fv.x * arv.x + fv.y * arv.y;
#pragma unroll
    for (int o = 16; o; o >>= 1) {
        sl += __shfl_xor_sync(0xffffffffu, sl, o);
        sr += __shfl_xor_sync(0xffffffffu, sr, o);
    }
    if (lane == 0) {
        g_el1[gw] = sl;
        g_er1[gw] = sr;
    }
}

// ---- fused store: elu(x) written as tf32 hi/lo split (h1 only feeds GEMM1) ----
__device__ __forceinline__ void store_elu_split(size_t idx, float v) {
    float e = v > 0.f ? v : __expf(v) - 1.f;
    uint32_t h, l;
    tf32split(e, h, l);
    g_spA_h[idx] = __uint_as_float(h);
    g_spA_l[idx] = __uint_as_float(l);
}

// ---------------- layer-0 softmax + aggregation + ELU + split: block per dst ----------------
__global__ void __launch_bounds__(256) gat_agg0_kernel()
{
    const int n = blockIdx.x;
    const int beg = g_rowoff[n];
    const int deg = g_rowoff[n + 1] - beg;
    const int tid = threadIdx.x;

    if (deg == 0) {   // elu(0) = 0 -> split(0) = (0,0)
        g_spA_h[(size_t)n * D0 + tid] = 0.f;
        g_spA_l[(size_t)n * D0 + tid] = 0.f;
        g_spA_h[(size_t)n * D0 + tid + 256] = 0.f;
        g_spA_l[(size_t)n * D0 + tid + 256] = 0.f;
        return;
    }

    __shared__ float s_alpha[HEADS][MAXDEG];
    __shared__ int   s_src[MAXDEG];
    __shared__ float s_m[HEADS], s_rinv[HEADS];

    const int h = tid >> 5;
    const int lane = tid & 31;
    const float ern = g_er0[n * HEADS + h];

    const int c0 = tid, c1 = tid + 256;
    const int h0 = c0 >> 6, h1i = c1 >> 6;

    if (deg <= MAXDEG) {
        for (int j = tid; j < deg; j += 256) s_src[j] = g_csrsrc[beg + j];
        __syncthreads();

        float m = NEG_INF;
        for (int j = lane; j < deg; j += 32) {
            float e = lrelu(g_el0[s_src[j] * HEADS + h] + ern);
            s_alpha[h][j] = e;
            m = fmaxf(m, e);
        }
#pragma unroll
        for (int o = 16; o; o >>= 1) m = fmaxf(m, __shfl_xor_sync(0xffffffffu, m, o));
        float sum = 0.f;
        for (int j = lane; j < deg; j += 32) {
            float ex = __expf(s_alpha[h][j] - m);
            s_alpha[h][j] = ex;
            sum += ex;
        }
#pragma unroll
        for (int o = 16; o; o >>= 1) sum += __shfl_xor_sync(0xffffffffu, sum, o);
        float rinv = 1.f / fmaxf(sum, 1e-9f);
        for (int j = lane; j < deg; j += 32) s_alpha[h][j] *= rinv;
        __syncthreads();

        float acc0 = 0.f, acc1 = 0.f;
#pragma unroll 4
        for (int j = 0; j < deg; j++) {
            const float* fr = g_feat0 + (size_t)s_src[j] * D0;
            acc0 = fmaf(s_alpha[h0][j], fr[c0], acc0);
            acc1 = fmaf(s_alpha[h1i][j], fr[c1], acc1);
        }
        store_elu_split((size_t)n * D0 + c0, acc0);
        store_elu_split((size_t)n * D0 + c1, acc1);
    } else {
        // huge-degree fallback: recompute e, no SMEM caches
        float m = NEG_INF;
        for (int j = lane; j < deg; j += 32)
            m = fmaxf(m, lrelu(g_el0[g_csrsrc[beg + j] * HEADS + h] + ern));
#pragma unroll
        for (int o = 16; o; o >>= 1) m = fmaxf(m, __shfl_xor_sync(0xffffffffu, m, o));
        float sum = 0.f;
        for (int j = lane; j < deg; j += 32)
            sum += __expf(lrelu(g_el0[g_csrsrc[beg + j] * HEADS + h] + ern) - m);
#pragma unroll
        for (int o = 16; o; o >>= 1) sum += __shfl_xor_sync(0xffffffffu, sum, o);
        if (lane == 0) { s_m[h] = m; s_rinv[h] = 1.f / fmaxf(sum, 1e-9f); }
        __syncthreads();

        const float m0 = s_m[h0], r0 = s_rinv[h0];
        const float m1 = s_m[h1i], r1 = s_rinv[h1i];
        const float e0n = g_er0[n * HEADS + h0], e1n = g_er0[n * HEADS + h1i];
        float acc0 = 0.f, acc1 = 0.f;
        for (int j = 0; j < deg; j++) {
            int s = g_csrsrc[beg + j];
            float a0 = __expf(lrelu(g_el0[s * HEADS + h0] + e0n) - m0) * r0;
            float a1 = __expf(lrelu(g_el0[s * HEADS + h1i] + e1n) - m1) * r1;
            const float* fr = g_feat0 + (size_t)s * D0;
            acc0 = fmaf(a0, fr[c0], acc0);
            acc1 = fmaf(a1, fr[c1], acc1);
        }
        store_elu_split((size_t)n * D0 + c0, acc0);
        store_elu_split((size_t)n * D0 + c1, acc1);
    }
}

// ---------------- layer-1 softmax + aggregation (1 head, 64 dims): block per dst ----------------
__global__ void __launch_bounds__(64) gat_agg1_kernel(float* __restrict__ out)
{
    const int n = blockIdx.x;
    const int beg = g_rowoff[n];
    const int deg = g_rowoff[n + 1] - beg;
    const int tid = threadIdx.x;

    if (deg == 0) { out[(size_t)n * OUT_DIM + tid] = 0.f; return; }

    __shared__ float s_alpha[MAXDEG];
    __shared__ int   s_src[MAXDEG];
    __shared__ float s_mr[2];

    const float ern = g_er1[n];

    if (deg <= MAXDEG) {
        for (int j = tid; j < deg; j += 64) s_src[j] = g_csrsrc[beg + j];
        __syncthreads();
        if (tid < 32) {
            float m = NEG_INF;
            for (int j = tid; j < deg; j += 32) {
                float e = lrelu(g_el1[s_src[j]] + ern);
                s_alpha[j] = e;
                m = fmaxf(m, e);
            }
#pragma unroll
            for (int o = 16; o; o >>= 1) m = fmaxf(m, __shfl_xor_sync(0xffffffffu, m, o));
            float sum = 0.f;
            for (int j = tid; j < deg; j += 32) {
                float ex = __expf(s_alpha[j] - m);
                s_alpha[j] = ex;
                sum += ex;
            }
#pragma unroll
            for (int o = 16; o; o >>= 1) sum += __shfl_xor_sync(0xffffffffu, sum, o);
            float rinv = 1.f / fmaxf(sum, 1e-9f);
            for (int j = tid; j < deg; j += 32) s_alpha[j] *= rinv;
        }
        __syncthreads();
        float acc = 0.f;
#pragma unroll 4
        for (int j = 0; j < deg; j++)
            acc = fmaf(s_alpha[j], g_feat1[(size_t)s_src[j] * OUT_DIM + tid], acc);
        out[(size_t)n * OUT_DIM + tid] = acc;
    } else {
        if (tid < 32) {
            float m = NEG_INF;
            for (int j = tid; j < deg; j += 32)
                m = fmaxf(m, lrelu(g_el1[g_csrsrc[beg + j]] + ern));
#pragma unroll
            for (int o = 16; o; o >>= 1) m = fmaxf(m, __shfl_xor_sync(0xffffffffu, m, o));
            float sum = 0.f;
            for (int j = tid; j < deg; j += 32)
                sum += __expf(lrelu(g_el1[g_csrsrc[beg + j]] + ern) - m);
#pragma unroll
            for (int o = 16; o; o >>= 1) sum += __shfl_xor_sync(0xffffffffu, sum, o);
            if (tid == 0) { s_mr[0] = m; s_mr[1] = 1.f / fmaxf(sum, 1e-9f); }
        }
        __syncthreads();
        const float m = s_mr[0], rinv = s_mr[1];
        float acc = 0.f;
        for (int j = 0; j < deg; j++) {
            int s = g_csrsrc[beg + j];
            float a = __expf(lrelu(g_el1[s] + ern) - m) * rinv;
            acc = fmaf(a, g_feat1[(size_t)s * OUT_DIM + tid], acc);
        }
        out[(size_t)n * OUT_DIM + tid] = acc;
    }
}

// ---------------- launch ----------------
extern "C" void kernel_launch(void* const* d_in, const int* in_sizes, int n_in,
                              void* d_out, int out_size)
{
    const float* features = (const float*)d_in[0];
    const int*   src      = (const int*)d_in[1];
    const int*   dst      = (const int*)d_in[2];
    const float* W0       = (const float*)d_in[3];
    const float* al0      = (const float*)d_in[4];
    const float* ar0      = (const float*)d_in[5];
    const float* W1       = (const float*)d_in[6];
    const float* al1      = (const float*)d_in[7];
    const float* ar1      = (const float*)d_in[8];
    float* out = (float*)d_out;

    float *feat0p = nullptr, *feat1p = nullptr;
    float *spAh = nullptr, *spAl = nullptr, *spBh = nullptr, *spBl = nullptr;
    cudaGetSymbolAddress((void**)&feat0p, g_feat0);
    cudaGetSymbolAddress((void**)&feat1p, g_feat1);
    cudaGetSymbolAddress((void**)&spAh,   g_spA_h);
    cudaGetSymbolAddress((void**)&spAl,   g_spA_l);
    cudaGetSymbolAddress((void**)&spBh,   g_spB_h);
    cudaGetSymbolAddress((void**)&spBl,   g_spB_l);

    cudaFuncSetAttribute(tf32ps_gemm_kernel,
                         cudaFuncAttributeMaxDynamicSharedMemorySize, GEMM_SMEM);

    // CSR by dst
    zero_counts_kernel<<<(N_NODES + 255) / 256, 256>>>();
    count_kernel<<<(N_EDGES + 255) / 256, 256>>>(dst);
    scan_kernel<<<1, 1024>>>();
    scatter_kernel<<<(N_EDGES + 255) / 256, 256>>>(src, dst);

    const int mblocks = (N_NODES + TBM - 1) / TBM;   // 157

    // layer 0: pre-split inputs, then pure-tf32 GEMM
    {
        int n4 = N_NODES * IN_FEATS / 4;
        split_tf32_kernel<<<(n4 + 255) / 256, 256>>>(
            (const float4*)features, (float4*)spAh, (float4*)spAl, n4);
        int w4 = IN_FEATS * D0 / 4;
        split_tf32_kernel<<<(w4 + 255) / 256, 256>>>(
            (const float4*)W0, (float4*)spBh, (float4*)spBl, w4);
    }
    tf32ps_gemm_kernel<<<dim3(D0 / TBN, mblocks), 256, GEMM_SMEM>>>(
        spAh, spAl, spBh, spBl, feat0p, N_NODES, D0, IN_FEATS);
    eler0_kernel<<<N_NODES, 256>>>(al0, ar0);
    gat_agg0_kernel<<<N_NODES, 256>>>();   // writes elu(h1) splits into spA

    // layer 1: split W1 (spA already holds split elu(h1))
    {
        int w4 = D0 * OUT_DIM / 4;
        split_tf32_kernel<<<(w4 + 255) / 256, 256>>>(
            (const float4*)W1, (float4*)spBh, (float4*)spBl, w4);
    }
    tf32ps_gemm_kernel<<<dim3(OUT_DIM / TBN, mblocks), 256, GEMM_SMEM>>>(
        spAh, spAl, spBh, spBl, feat1p, N_NODES, OUT_DIM, D0);
    eler1_kernel<<<(N_NODES + 7) / 8, 256>>>(al1, ar1);
    gat_agg1_kernel<<<N_NODES, 64>>>(out);
}

// round 8
// speedup vs baseline: 1.0035x; 1.0031x over previous
#include <cuda_runtime.h>
#include <cuda_bf16.h>
#include <cstdint>

#define N_NODES 20000
#define N_EDGES 320000
#define IN_FEATS 512
#define HIDDEN 64
#define HEADS 8
#define D0 512           // HEADS*HIDDEN
#define OUT_DIM 64
#define NEG_SLOPE 0.2f
#define MAXDEG 512

// ---------------- scratch (device globals; no allocation allowed) ----------------
__device__ float g_feat0[(size_t)N_NODES * D0];      // layer0 projected feats [N, 8*64]
__device__ float g_feat1[(size_t)N_NODES * OUT_DIM]; // layer1 projected feats [N, 64]
__device__ float g_spA_h[(size_t)N_NODES * D0];      // tf32-split A (features, then elu(h1))
__device__ float g_spA_l[(size_t)N_NODES * D0];
__device__ float g_spB_h[IN_FEATS * D0];             // tf32-split W (W0, then W1)
__device__ float g_spB_l[IN_FEATS * D0];
__device__ float g_el0[N_NODES * HEADS];
__device__ float g_er0[N_NODES * HEADS];
__device__ float g_el1[N_NODES];
__device__ float g_er1[N_NODES];
__device__ int   g_counts[N_NODES];
__device__ int   g_rowoff[N_NODES + 1];
__device__ int   g_cursor[N_NODES];
__device__ int   g_csrsrc[N_EDGES];

__device__ __forceinline__ float lrelu(float x) { return x > 0.f ? x : NEG_SLOPE * x; }
#define NEG_INF __int_as_float(0xff800000)

__device__ __forceinline__ void tf32split(float v, uint32_t& h, uint32_t& l) {
    uint32_t uh;
    asm("cvt.rna.tf32.f32 %0, %1;" : "=r"(uh) : "f"(v));
    float fl = v - __uint_as_float(uh);
    uint32_t ul;
    asm("cvt.rna.tf32.f32 %0, %1;" : "=r"(ul) : "f"(fl));
    h = uh; l = ul;
}

// ---------------- CSR build ----------------
__global__ void zero_counts_kernel() {
    int i = blockIdx.x * blockDim.x + threadIdx.x;
    if (i < N_NODES) g_counts[i] = 0;
}

__global__ void count_kernel(const int* __restrict__ dst) {
    int e = blockIdx.x * blockDim.x + threadIdx.x;
    if (e < N_EDGES) atomicAdd(&g_counts[dst[e]], 1);
}

__global__ void scan_kernel() {
    __shared__ int s[1024];
    const int tid = threadIdx.x;
    const int CH = (N_NODES + 1023) / 1024;   // 20
    int b = tid * CH;
    int e = min(b + CH, N_NODES);
    int local = 0;
    for (int i = b; i < e; i++) local += g_counts[i];
    s[tid] = local;
    __syncthreads();
    for (int off = 1; off < 1024; off <<= 1) {
        int add = (tid >= off) ? s[tid - off] : 0;
        __syncthreads();
        s[tid] += add;
        __syncthreads();
    }
    int run = s[tid] - local;                 // exclusive prefix
    for (int i = b; i < e; i++) {
        g_rowoff[i] = run;
        g_cursor[i] = run;
        run += g_counts[i];
    }
    if (tid == 1023) g_rowoff[N_NODES] = s[1023];
}

__global__ void scatter_kernel(const int* __restrict__ src, const int* __restrict__ dst) {
    int e = blockIdx.x * blockDim.x + threadIdx.x;
    if (e < N_EDGES) {
        int pos = atomicAdd(&g_cursor[dst[e]], 1);
        g_csrsrc[pos] = src[e];
    }
}

// ---------------- tf32 pre-split: v -> (hi, lo) as fp32-compatible bit patterns ----------------
__global__ void split_tf32_kernel(const float4* __restrict__ in,
                                  float4* __restrict__ hi, float4* __restrict__ lo, int n4)
{
    int i = blockIdx.x * blockDim.x + threadIdx.x;
    if (i >= n4) return;
    float4 v = in[i];
    uint32_t hx, lx, hy, ly, hz, lz, hw, lw;
    tf32split(v.x, hx, lx);
    tf32split(v.y, hy, ly);
    tf32split(v.z, hz, lz);
    tf32split(v.w, hw, lw);
    hi[i] = make_float4(__uint_as_float(hx), __uint_as_float(hy),
                        __uint_as_float(hz), __uint_as_float(hw));
    lo[i] = make_float4(__uint_as_float(lx), __uint_as_float(ly),
                        __uint_as_float(lz), __uint_as_float(lw));
}

// ================= pure-tf32 3-term tensor-core GEMM (pre-split inputs) =================
// C[M,N] = A[M,K]*B[K,N] with A=Ah+Al, B=Bh+Bl already split to tf32.
// C ~= Ah*Bh + Ah*Bl + Al*Bh. Tiles: BM=128, BN=64, BK=16; 256 thr = 8 warps, 32x32/warp.
#define TBM 128
#define TBN 64
#define TBK 16
#define A_STRIDE 20
#define B_STRIDE 72
#define SA_BUF (TBM * A_STRIDE)           // floats per buffer
#define SB_BUF (TBK * B_STRIDE)
#define GEMM_SMEM ((2 * SA_BUF * 2 + 2 * SB_BUF * 2) * 4)   // bytes = 59392

__device__ __forceinline__ void cpasync16(void* smem, const void* g, bool valid) {
    uint32_t sa = (uint32_t)__cvta_generic_to_shared(smem);
    int sz = valid ? 16 : 0;
    asm volatile("cp.async.cg.shared.global [%0], [%1], 16, %2;" :: "r"(sa), "l"(g), "r"(sz));
}

__device__ __forceinline__ void mma8(float* c, const uint32_t* a, const uint32_t* b) {
    asm volatile(
        "mma.sync.aligned.m16n8k8.row.col.f32.tf32.tf32.f32 "
        "{%0,%1,%2,%3}, {%4,%5,%6,%7}, {%8,%9}, {%0,%1,%2,%3};"
        : "+f"(c[0]), "+f"(c[1]), "+f"(c[2]), "+f"(c[3])
        : "r"(a[0]), "r"(a[1]), "r"(a[2]), "r"(a[3]), "r"(b[0]), "r"(b[1]));
}

__global__ void __launch_bounds__(256, 2) tf32ps_gemm_kernel(
    const float* __restrict__ Ah, const float* __restrict__ Al,
    const float* __restrict__ Bh, const float* __restrict__ Bl,
    float* __restrict__ C, int M, int N, int K)
{
    extern __shared__ float sm[];
    float* sAh = sm;
    float* sAl = sAh + 2 * SA_BUF;
    float* sBh = sAl + 2 * SA_BUF;
    float* sBl = sBh + 2 * SB_BUF;

    const int bm = blockIdx.y * TBM;
    const int bn = blockIdx.x * TBN;
    const int tid = threadIdx.x;
    const int lane = tid & 31;
    const int warp = tid >> 5;
    const int wm = warp >> 1;       // 0..3
    const int wn = warp & 1;        // 0..1
    const int quad = lane >> 2;     // 0..7
    const int kq = lane & 3;        // 0..3

    const int a_m  = tid >> 2;            // 0..63  (two passes: +64)
    const int a_kc = (tid & 3) << 2;      // 0,4,8,12
    const int b_k  = tid >> 4;            // 0..15
    const int b_nc = (tid & 15) << 2;     // 0..60

    float acc[2][4][4];
#pragma unroll
    for (int mi = 0; mi < 2; mi++)
#pragma unroll
        for (int ni = 0; ni < 4; ni++)
#pragma unroll
            for (int r = 0; r < 4; r++) acc[mi][ni][r] = 0.f;

    const int T = K / TBK;

    // ---- prologue: stage tile 0 into buffer 0 ----
    {
#pragma unroll
        for (int p = 0; p < 2; p++) {
            int m = a_m + (p << 6);
            bool ok = (bm + m) < M;
            size_t go = (size_t)(bm + m) * K + a_kc;
            int so = m * A_STRIDE + a_kc;
            cpasync16(&sAh[so], Ah + go, ok);
            cpasync16(&sAl[so], Al + go, ok);
        }
        size_t gbo = (size_t)b_k * N + bn + b_nc;
        int sbo = b_k * B_STRIDE + b_nc;
        cpasync16(&sBh[sbo], Bh + gbo, true);
        cpasync16(&sBl[sbo], Bl + gbo, true);
        asm volatile("cp.async.commit_group;");
    }

    for (int t = 0; t < T; t++) {
        const int cur = t & 1;
        if (t + 1 < T) {
            const int nxt = cur ^ 1;
            const int kt = (t + 1) * TBK;
#pragma unroll
            for (int p = 0; p < 2; p++) {
                int m = a_m + (p << 6);
                bool ok = (bm + m) < M;
                size_t go = (size_t)(bm + m) * K + kt + a_kc;
                int so = nxt * SA_BUF + m * A_STRIDE + a_kc;
                cpasync16(&sAh[so], Ah + go, ok);
                cpasync16(&sAl[so], Al + go, ok);
            }
            size_t gbo = (size_t)(kt + b_k) * N + bn + b_nc;
            int sbo = nxt * SB_BUF + b_k * B_STRIDE + b_nc;
            cpasync16(&sBh[sbo], Bh + gbo, true);
            cpasync16(&sBl[sbo], Bl + gbo, true);
            asm volatile("cp.async.commit_group;");
            asm volatile("cp.async.wait_group 1;");
        } else {
            asm volatile("cp.async.wait_group 0;");
        }
        __syncthreads();

#pragma unroll
        for (int ks = 0; ks < 2; ks++) {
            const int kb = ks * 8 + kq;
            uint32_t ah[2][4], al_[2][4];
#pragma unroll
            for (int mi = 0; mi < 2; mi++) {
#pragma unroll
                for (int r = 0; r < 4; r++) {
                    int row = wm * 32 + mi * 16 + quad + ((r & 1) << 3);
                    int col = kb + ((r >> 1) << 2);
                    int idx = cur * SA_BUF + row * A_STRIDE + col;
                    ah[mi][r]  = __float_as_uint(sAh[idx]);
                    al_[mi][r] = __float_as_uint(sAl[idx]);
                }
            }
            uint32_t bh[4][2], bl[4][2];
#pragma unroll
            for (int ni = 0; ni < 4; ni++) {
#pragma unroll
                for (int r = 0; r < 2; r++) {
                    int krow = kb + (r << 2);
                    int ncol = wn * 32 + ni * 8 + quad;
                    int idx = cur * SB_BUF + krow * B_STRIDE + ncol;
                    bh[ni][r] = __float_as_uint(sBh[idx]);
                    bl[ni][r] = __float_as_uint(sBl[idx]);
                }
            }
            // three terms, 8 independent accs between reuses of each acc
#pragma unroll
            for (int mi = 0; mi < 2; mi++)
#pragma unroll
                for (int ni = 0; ni < 4; ni++) mma8(acc[mi][ni], ah[mi], bh[ni]);
#pragma unroll
            for (int mi = 0; mi < 2; mi++)
#pragma unroll
                for (int ni = 0; ni < 4; ni++) mma8(acc[mi][ni], ah[mi], bl[ni]);
#pragma unroll
            for (int mi = 0; mi < 2; mi++)
#pragma unroll
                for (int ni = 0; ni < 4; ni++) mma8(acc[mi][ni], al_[mi], bh[ni]);
        }
        __syncthreads();
    }

    // ---- epilogue ----
#pragma unroll
    for (int mi = 0; mi < 2; mi++) {
#pragma unroll
        for (int ni = 0; ni < 4; ni++) {
            int row0 = bm + wm * 32 + mi * 16 + quad;
            int col = bn + wn * 32 + ni * 8 + kq * 2;
            if (row0 < M)
                *(float2*)(C + (size_t)row0 * N + col) =
                    make_float2(acc[mi][ni][0], acc[mi][ni][1]);
            int row1 = row0 + 8;
            if (row1 < M)
                *(float2*)(C + (size_t)row1 * N + col) =
                    make_float2(acc[mi][ni][2], acc[mi][ni][3]);
        }
    }
}

// ---------------- el/er for layer 0: warp per (node, head) ----------------
__global__ void __launch_bounds__(256) eler0_kernel(const float* __restrict__ al,
                                                    const float* __restrict__ ar)
{
    const int n = blockIdx.x;
    const int h = threadIdx.x >> 5;
    const int lane = threadIdx.x & 31;
    const float* f = g_feat0 + (size_t)n * D0 + h * HIDDEN;
    float2 fv = *(const float2*)(f + lane * 2);
    float2 alv = *(const float2*)(al + h * HIDDEN + lane * 2);
    float2 arv = *(const float2*)(ar + h * HIDDEN + lane * 2);
    float sl = fv.x * alv.x + fv.y * alv.y;
    float sr = fv.x * arv.x + fv.y * arv.y;
#pragma unroll
    for (int o = 16; o; o >>= 1) {
        sl += __shfl_xor_sync(0xffffffffu, sl, o);
        sr += __shfl_xor_sync(0xffffffffu, sr, o);
    }
    if (lane == 0) {
        g_el0[n * HEADS + h] = sl;
        g_er0[n * HEADS + h] = sr;
    }
}

// ---------------- el/er for layer 1: warp per node ----------------
__global__ void __launch_bounds__(256) eler1_kernel(const float* __restrict__ al,
                                                    const float* __restrict__ ar)
{
    const int gw = blockIdx.x * 8 + (threadIdx.x >> 5);
    const int lane = threadIdx.x & 31;
    if (gw >= N_NODES) return;
    const float* f = g_feat1 + (size_t)gw * OUT_DIM;
    float2 fv = *(const float2*)(f + lane * 2);
    float2 alv = *(const float2*)(al + lane * 2);
    float2 arv = *(const float2*)(ar + lane * 2);
    float sl = fv.x * alv.x + fv.y * alv.y;
    float sr = fv.x * arv.x + fv.y * arv.y;
#pragma unroll
    for (int o = 16; o; o >>= 1) {
        sl += __shfl_xor_sync(0xffffffffu, sl, o);
        sr += __shfl_xor_sync(0xffffffffu, sr, o);
    }
    if (lane == 0) {
        g_el1[gw] = sl;
        g_er1[gw] = sr;
    }
}

// ---- fused store: elu(x) written as tf32 hi/lo split (h1 only feeds GEMM1) ----
__device__ __forceinline__ void store_elu_split(size_t idx, float v) {
    float e = v > 0.f ? v : __expf(v) - 1.f;
    uint32_t h, l;
    tf32split(e, h, l);
    g_spA_h[idx] = __uint_as_float(h);
    g_spA_l[idx] = __uint_as_float(l);
}

// ---------------- layer-0 softmax + aggregation + ELU + split: block per dst ----------------
__global__ void __launch_bounds__(256) gat_agg0_kernel()
{
    const int n = blockIdx.x;
    const int beg = g_rowoff[n];
    const int deg = g_rowoff[n + 1] - beg;
    const int tid = threadIdx.x;

    if (deg == 0) {   // elu(0) = 0 -> split(0) = (0,0)
        g_spA_h[(size_t)n * D0 + tid] = 0.f;
        g_spA_l[(size_t)n * D0 + tid] = 0.f;
        g_spA_h[(size_t)n * D0 + tid + 256] = 0.f;
        g_spA_l[(size_t)n * D0 + tid + 256] = 0.f;
        return;
    }

    __shared__ float s_alpha[HEADS][MAXDEG];
    __shared__ int   s_src[MAXDEG];
    __shared__ float s_m[HEADS], s_rinv[HEADS];

    const int h = tid >> 5;
    const int lane = tid & 31;
    const float ern = g_er0[n * HEADS + h];

    const int c0 = tid, c1 = tid + 256;
    const int h0 = c0 >> 6, h1i = c1 >> 6;

    if (deg <= MAXDEG) {
        for (int j = tid; j < deg; j += 256) s_src[j] = g_csrsrc[beg + j];
        __syncthreads();

        float m = NEG_INF;
        for (int j = lane; j < deg; j += 32) {
            float e = lrelu(g_el0[s_src[j] * HEADS + h] + ern);
            s_alpha[h][j] = e;
            m = fmaxf(m, e);
        }
#pragma unroll
        for (int o = 16; o; o >>= 1) m = fmaxf(m, __shfl_xor_sync(0xffffffffu, m, o));
        float sum = 0.f;
        for (int j = lane; j < deg; j += 32) {
            float ex = __expf(s_alpha[h][j] - m);
            s_alpha[h][j] = ex;
            sum += ex;
        }
#pragma unroll
        for (int o = 16; o; o >>= 1) sum += __shfl_xor_sync(0xffffffffu, sum, o);
        float rinv = 1.f / fmaxf(sum, 1e-9f);
        for (int j = lane; j < deg; j += 32) s_alpha[h][j] *= rinv;
        __syncthreads();

        float acc0 = 0.f, acc1 = 0.f;
#pragma unroll 4
        for (int j = 0; j < deg; j++) {
            const float* fr = g_feat0 + (size_t)s_src[j] * D0;
            acc0 = fmaf(s_alpha[h0][j], fr[c0], acc0);
            acc1 = fmaf(s_alpha[h1i][j], fr[c1], acc1);
        }
        store_elu_split((size_t)n * D0 + c0, acc0);
        store_elu_split((size_t)n * D0 + c1, acc1);
    } else {
        // huge-degree fallback: recompute e, no SMEM caches
        float m = NEG_INF;
        for (int j = lane; j < deg; j += 32)
            m = fmaxf(m, lrelu(g_el0[g_csrsrc[beg + j] * HEADS + h] + ern));
#pragma unroll
        for (int o = 16; o; o >>= 1) m = fmaxf(m, __shfl_xor_sync(0xffffffffu, m, o));
        float sum = 0.f;
        for (int j = lane; j < deg; j += 32)
            sum += __expf(lrelu(g_el0[g_csrsrc[beg + j] * HEADS + h] + ern) - m);
#pragma unroll
        for (int o = 16; o; o >>= 1) sum += __shfl_xor_sync(0xffffffffu, sum, o);
        if (lane == 0) { s_m[h] = m; s_rinv[h] = 1.f / fmaxf(sum, 1e-9f); }
        __syncthreads();

        const float m0 = s_m[h0], r0 = s_rinv[h0];
        const float m1 = s_m[h1i], r1 = s_rinv[h1i];
        const float e0n = g_er0[n * HEADS + h0], e1n = g_er0[n * HEADS + h1i];
        float acc0 = 0.f, acc1 = 0.f;
        for (int j = 0; j < deg; j++) {
            int s = g_csrsrc[beg + j];
            float a0 = __expf(lrelu(g_el0[s * HEADS + h0] + e0n) - m0) * r0;
            float a1 = __expf(lrelu(g_el0[s * HEADS + h1i] + e1n) - m1) * r1;
            const float* fr = g_feat0 + (size_t)s * D0;
            acc0 = fmaf(a0, fr[c0], acc0);
            acc1 = fmaf(a1, fr[c1], acc1);
        }
        store_elu_split((size_t)n * D0 + c0, acc0);
        store_elu_split((size_t)n * D0 + c1, acc1);
    }
}

// ---------------- layer-1 softmax + aggregation (1 head, 64 dims): block per dst ----------------
__global__ void __launch_bounds__(64) gat_agg1_kernel(float* __restrict__ out)
{
    const int n = blockIdx.x;
    const int beg = g_rowoff[n];
    const int deg = g_rowoff[n + 1] - beg;
    const int tid = threadIdx.x;

    if (deg == 0) { out[(size_t)n * OUT_DIM + tid] = 0.f; return; }

    __shared__ float s_alpha[MAXDEG];
    __shared__ int   s_src[MAXDEG];
    __shared__ float s_mr[2];

    const float ern = g_er1[n];

    if (deg <= MAXDEG) {
        for (int j = tid; j < deg; j += 64) s_src[j] = g_csrsrc[beg + j];
        __syncthreads();
        if (tid < 32) {
            float m = NEG_INF;
            for (int j = tid; j < deg; j += 32) {
                float e = lrelu(g_el1[s_src[j]] + ern);
                s_alpha[j] = e;
                m = fmaxf(m, e);
            }
#pragma unroll
            for (int o = 16; o; o >>= 1) m = fmaxf(m, __shfl_xor_sync(0xffffffffu, m, o));
            float sum = 0.f;
            for (int j = tid; j < deg; j += 32) {
                float ex = __expf(s_alpha[j] - m);
                s_alpha[j] = ex;
                sum += ex;
            }
#pragma unroll
            for (int o = 16; o; o >>= 1) sum += __shfl_xor_sync(0xffffffffu, sum, o);
            float rinv = 1.f / fmaxf(sum, 1e-9f);
            for (int j = tid; j < deg; j += 32) s_alpha[j] *= rinv;
        }
        __syncthreads();
        float acc = 0.f;
#pragma unroll 4
        for (int j = 0; j < deg; j++)
            acc = fmaf(s_alpha[j], g_feat1[(size_t)s_src[j] * OUT_DIM + tid], acc);
        out[(size_t)n * OUT_DIM + tid] = acc;
    } else {
        if (tid < 32) {
            float m = NEG_INF;
            for (int j = tid; j < deg; j += 32)
                m = fmaxf(m, lrelu(g_el1[g_csrsrc[beg + j]] + ern));
#pragma unroll
            for (int o = 16; o; o >>= 1) m = fmaxf(m, __shfl_xor_sync(0xffffffffu, m, o));
            float sum = 0.f;
            for (int j = tid; j < deg; j += 32)
                sum += __expf(lrelu(g_el1[g_csrsrc[beg + j]] + ern) - m);
#pragma unroll
            for (int o = 16; o; o >>= 1) sum += __shfl_xor_sync(0xffffffffu, sum, o);
            if (tid == 0) { s_mr[0] = m; s_mr[1] = 1.f / fmaxf(sum, 1e-9f); }
        }
        __syncthreads();
        const float m = s_mr[0], rinv = s_mr[1];
        float acc = 0.f;
        for (int j = 0; j < deg; j++) {
            int s = g_csrsrc[beg + j];
            float a = __expf(lrelu(g_el1[s] + ern) - m) * rinv;
            acc = fmaf(a, g_feat1[(size_t)s * OUT_DIM + tid], acc);
        }
        out[(size_t)n * OUT_DIM + tid] = acc;
    }
}

// ---------------- launch ----------------
extern "C" void kernel_launch(void* const* d_in, const int* in_sizes, int n_in,
                              void* d_out, int out_size)
{
    const float* features = (const float*)d_in[0];
    const int*   src      = (const int*)d_in[1];
    const int*   dst      = (const int*)d_in[2];
    const float* W0       = (const float*)d_in[3];
    const float* al0      = (const float*)d_in[4];
    const float* ar0      = (const float*)d_in[5];
    const float* W1       = (const float*)d_in[6];
    const float* al1      = (const float*)d_in[7];
    const float* ar1      = (const float*)d_in[8];
    float* out = (float*)d_out;

    float *feat0p = nullptr, *feat1p = nullptr;
    float *spAh = nullptr, *spAl = nullptr, *spBh = nullptr, *spBl = nullptr;
    cudaGetSymbolAddress((void**)&feat0p, g_feat0);
    cudaGetSymbolAddress((void**)&feat1p, g_feat1);
    cudaGetSymbolAddress((void**)&spAh,   g_spA_h);
    cudaGetSymbolAddress((void**)&spAl,   g_spA_l);
    cudaGetSymbolAddress((void**)&spBh,   g_spB_h);
    cudaGetSymbolAddress((void**)&spBl,   g_spB_l);

    cudaFuncSetAttribute(tf32ps_gemm_kernel,
                         cudaFuncAttributeMaxDynamicSharedMemorySize, GEMM_SMEM);

    // CSR by dst
    zero_counts_kernel<<<(N_NODES + 255) / 256, 256>>>();
    count_kernel<<<(N_EDGES + 255) / 256, 256>>>(dst);
    scan_kernel<<<1, 1024>>>();
    scatter_kernel<<<(N_EDGES + 255) / 256, 256>>>(src, dst);

    const int mblocks = (N_NODES + TBM - 1) / TBM;   // 157

    // layer 0: pre-split inputs, then pure-tf32 GEMM
    {
        int n4 = N_NODES * IN_FEATS / 4;
        split_tf32_kernel<<<(n4 + 255) / 256, 256>>>(
            (const float4*)features, (float4*)spAh, (float4*)spAl, n4);
        int w4 = IN_FEATS * D0 / 4;
        split_tf32_kernel<<<(w4 + 255) / 256, 256>>>(
            (const float4*)W0, (float4*)spBh, (float4*)spBl, w4);
    }
    tf32ps_gemm_kernel<<<dim3(D0 / TBN, mblocks), 256, GEMM_SMEM>>>(
        spAh, spAl, spBh, spBl, feat0p, N_NODES, D0, IN_FEATS);
    eler0_kernel<<<N_NODES, 256>>>(al0, ar0);
    gat_agg0_kernel<<<N_NODES, 256>>>();   // writes elu(h1) splits into spA

    // layer 1: split W1 (spA already holds split elu(h1))
    {
        int w4 = D0 * OUT_DIM / 4;
        split_tf32_kernel<<<(w4 + 255) / 256, 256>>>(
            (const float4*)W1, (float4*)spBh, (float4*)spBl, w4);
    }
    tf32ps_gemm_kernel<<<dim3(OUT_DIM / TBN, mblocks), 256, GEMM_SMEM>>>(
        spAh, spAl, spBh, spBl, feat1p, N_NODES, OUT_DIM, D0);
    eler1_kernel<<<(N_NODES + 7) / 8, 256>>>(al1, ar1);
    gat_agg1_kernel<<<N_NODES, 64>>>(out);
}